// round 15
// baseline (speedup 1.0000x reference)
#include <cuda_runtime.h>
#include <cuda_fp16.h>
#include <cstdint>

// ---------------- problem constants ----------------
namespace {
constexpr int NB = 64;     // batch
constexpr int NS = 1024;   // sequence length
constexpr int NI = 512;    // input dim
constexpr int NH = 2048;   // hidden dim
constexpr int NO = 512;    // output dim
constexpr int BH = NB * NH;      // 131072 state elements

constexpr int GB = 128;          // persistent blocks (1/SM, co-resident)
constexpr int SK = 4;            // split-K chunks = cluster size
constexpr int KC = NH / SK;      // 512 K per recurrence block

// per-team partial sizing: 8 planes x 32 bands x 2048 floats
constexpr int PT_PLANE = 32 * 2048;          // 65536 floats per plane
constexpr int PT_TEAM  = 8 * PT_PLANE;       // 524288 floats per team

// k_recur smem: rows of 1024B (512 fp16) + 16B pad
constexpr int PITCH2 = 1040;
constexpr int R_W  = 0;                        // 64 rows (W chunk)
constexpr int R_BA = R_W + 64 * PITCH2;        // 32 rows (team A sigh)
constexpr int R_BB = R_BA + 32 * PITCH2;       // 32 rows (team B sigh)
constexpr int R_TOTAL = R_BB + 32 * PITCH2;    // 133120 B

// projection kernels: K=256 rows (512B) + 16B pad
constexpr int PITCH = 528;
constexpr int X_W  = 0;
constexpr int X_B  = X_W + 128 * PITCH;
constexpr int X_NS = X_B + 64 * PITCH;
constexpr int X_TOTAL = X_NS + 64 * 132 * 4;
constexpr int O_W = 0;
constexpr int O_B = O_W + 128 * PITCH;
constexpr int O_TOTAL = O_B + 64 * PITCH;
}

// ---------------- scratch (static device allocations) ----------------
__device__ float g_xwn[(size_t)NS * NB * NH];     // [t][h][b] xw + 0.1*noise
__device__ float g_hid_fb[(size_t)NB * NS * NH];  // fallback hidden storage
__device__ float g_part[2][2][PT_TEAM];           // [parity][team][plane|band|slot]
__device__ __half g_sigh[2][BH];                  // ping-pong sigmoid(h) fp16 [b][h]
__device__ __half g_wih[(size_t)NH * NI];         // W_ih fp16 [h][i]
__device__ __half g_who[(size_t)NO * NH];         // W_ho fp16 [o][h]

// sync state
__device__ unsigned g_slots[GB];
__device__ unsigned g_flag;
__device__ unsigned g_cnt[2][4][8];   // [team][chunk], 32B-strided

// ---------------- helpers ----------------
__device__ __forceinline__ float sigmoidf_(float x) {
    return 1.0f / (1.0f + __expf(-x));
}
__device__ __forceinline__ unsigned h2pack(float a, float b) {
    __half2 t;
    t.x = __float2half_rn(a);
    t.y = __float2half_rn(b);
    return *reinterpret_cast<unsigned*>(&t);
}
__device__ __forceinline__ uint32_t smem_u32(const void* p) {
    uint32_t a;
    asm("{ .reg .u64 t; cvta.to.shared.u64 t, %1; cvt.u32.u64 %0, t; }"
        : "=r"(a) : "l"(p));
    return a;
}
__device__ __forceinline__ void ldsm4(unsigned* r, uint32_t addr) {
    asm volatile("ldmatrix.sync.aligned.m8n8.x4.shared.b16 {%0,%1,%2,%3}, [%4];"
                 : "=r"(r[0]), "=r"(r[1]), "=r"(r[2]), "=r"(r[3]) : "r"(addr));
}
__device__ __forceinline__ void mma_f16(float* d, const unsigned* a, const unsigned* b) {
    asm("mma.sync.aligned.m16n8k16.row.col.f32.f16.f16.f32 "
        "{%0,%1,%2,%3}, {%4,%5,%6,%7}, {%8,%9}, {%0,%1,%2,%3};"
        : "+f"(d[0]), "+f"(d[1]), "+f"(d[2]), "+f"(d[3])
        : "r"(a[0]), "r"(a[1]), "r"(a[2]), "r"(a[3]), "r"(b[0]), "r"(b[1]));
}

// ---------------- sync primitives ----------------
__device__ __forceinline__ void arrive(unsigned* p) {
    asm volatile("red.release.gpu.global.add.u32 [%0], %1;"
                 :: "l"(p), "r"(1u) : "memory");
}
__device__ __forceinline__ void pollge(unsigned* p, unsigned target) {
    unsigned v;
    do {
        asm volatile("ld.acquire.gpu.global.u32 %0, [%1];"
                     : "=r"(v) : "l"(p) : "memory");
    } while (v < target);
}
__device__ __forceinline__ void cluster_arrive_() {
    asm volatile("barrier.cluster.arrive.aligned;" ::: "memory");
}
__device__ __forceinline__ void cluster_wait_() {
    asm volatile("barrier.cluster.wait.aligned;" ::: "memory");
}

// flag-array full barrier (used twice per launch; state returns to 0)
__device__ __forceinline__ void flag_barrier(unsigned want) {
    __syncthreads();
    if (threadIdx.x == 0) {
        asm volatile("st.release.gpu.global.u32 [%0], %1;"
                     :: "l"(&g_slots[blockIdx.x]), "r"(want) : "memory");
    }
    if (blockIdx.x == 0) {
        if (threadIdx.x < GB) {
            unsigned v;
            do {
                asm volatile("ld.acquire.gpu.global.u32 %0, [%1];"
                             : "=r"(v) : "l"(&g_slots[threadIdx.x]) : "memory");
            } while (v != want);
        }
        __syncthreads();
        if (threadIdx.x == 0) {
            asm volatile("st.release.gpu.global.u32 [%0], %1;"
                         :: "l"(&g_flag), "r"(want) : "memory");
        }
    } else {
        if (threadIdx.x == 0) {
            unsigned v;
            do {
                asm volatile("ld.acquire.gpu.global.u32 %0, [%1];"
                             : "=r"(v) : "l"(&g_flag) : "memory");
            } while (v != want);
        }
        __syncthreads();
    }
}

// ---------------- W_ih / W_ho fp32 -> fp16 conversion (one-time) ----------------
__global__ void __launch_bounds__(256) k_convW(const float* __restrict__ Wih,
                                               const float* __restrict__ Who) {
    const int idx = blockIdx.x * 256 + threadIdx.x;
    if (idx < NH * NI) {
        g_wih[idx] = __float2half_rn(Wih[idx]);
    } else {
        int i = idx - NH * NI;
        g_who[i] = __float2half_rn(Who[i]);
    }
}

// ---------------- persistent recurrence kernel (two-team pipeline) ----------------
// Teams = batch halves (A: b 0-31, B: b 32-63) — independent recurrences.
// Per iteration each CTA advances both teams one step; each team's counter
// propagation/skew is hidden behind the other team's GEMM/update.
__global__ void __launch_bounds__(256, 1) __cluster_dims__(SK, 1, 1)
k_recur(const float* __restrict__ h0, const float* __restrict__ Whh,
        float* __restrict__ hidden) {
    extern __shared__ __align__(1024) char sm[];
    const uint32_t smb = smem_u32(sm);
    const int tid = threadIdx.x;
    const int wid = tid >> 5;
    const int lane = tid & 31;
    const int bx = blockIdx.x;
    const int nt = bx >> 2;            // band 0..31 (cluster id)
    const int sk = bx & 3;             // k-chunk / cluster rank
    const int n0 = nt * 64;
    const int kbeg = sk * KC;
    const int myc = nt >> 3;           // chunk this band's sigh feeds

    if (bx == 0 && tid < 8) g_cnt[tid >> 2][tid & 3][0] = 0;

    // ---- one-time: stage W_hh chunk [64 rows x 512 k] fp16 into SMEM ----
    for (int it = 0; it < 8; it++) {
        const int r = it * 8 + wid;
        const float* wr = Whh + (size_t)(n0 + r) * NH + kbeg;
#pragma unroll
        for (int g = 0; g < 2; g++) {
            const int c = g * 256 + lane * 8;
            float4 v0 = *(const float4*)(wr + c);
            float4 v1 = *(const float4*)(wr + c + 4);
            uint4 H = make_uint4(h2pack(v0.x, v0.y), h2pack(v0.z, v0.w),
                                 h2pack(v1.x, v1.y), h2pack(v1.z, v1.w));
            *(uint4*)(sm + R_W + r * PITCH2 + c * 2) = H;
        }
    }

    // ---- update mapping: CTA sk updates fb = sk*512 + tid*2 of each team ----
    const int fb = (sk << 9) + (tid << 1);
    const int slot = fb >> 4, j0 = fb & 15;
    const int wmn = slot >> 5, lane_w = slot & 31;
    const int mi_u = j0 >> 3, ni_u = (j0 >> 2) & 1, jj = j0 & 3;   // jj in {0,2}
    const int hl = (wmn >> 1) * 32 + mi_u * 16 + (lane_w >> 2) + (jj ? 8 : 0);
    const int bA = (wmn & 1) * 16 + ni_u * 8 + (lane_w & 3) * 2;   // team A: 0..31
    const int h  = n0 + hl;
    const int bB = bA + 32;

    // ---- init state: h in registers (2 els per team), sigh[0] ----
    float2 hpA, hpB;
    hpA.x = h0[(size_t)(bA + 0) * NH + h];
    hpA.y = h0[(size_t)(bA + 1) * NH + h];
    hpB.x = h0[(size_t)(bB + 0) * NH + h];
    hpB.y = h0[(size_t)(bB + 1) * NH + h];
    g_sigh[0][(size_t)(bA + 0) * NH + h] = __float2half_rn(sigmoidf_(hpA.x));
    g_sigh[0][(size_t)(bA + 1) * NH + h] = __float2half_rn(sigmoidf_(hpA.y));
    g_sigh[0][(size_t)(bB + 0) * NH + h] = __float2half_rn(sigmoidf_(hpB.x));
    g_sigh[0][(size_t)(bB + 1) * NH + h] = __float2half_rn(sigmoidf_(hpB.y));

    flag_barrier(1);      // counter reset + init sigh visible

    // ---- GEMM constants: warps 2m x 2n x 2k, warp tile m32 x n16 x k256 ----
    const int wm = (wid >> 2) & 1;
    const int wn = (wid >> 1) & 1;
    const int wk = wid & 1;
    const uint32_t kwoff = (uint32_t)(wk * 512);   // byte offset of k-half
    const uint32_t aA = smb + R_W + kwoff +
        (uint32_t)((wm * 32 + (lane & 15)) * PITCH2 + ((lane >> 4) << 4));
    const uint32_t bRow = (uint32_t)((wn * 16 + (lane & 7) + ((lane >> 4) << 3)) * PITCH2 +
                                     (((lane >> 3) & 1) << 4));
    const uint32_t bAa = smb + R_BA + kwoff + bRow;
    const uint32_t bAb = smb + R_BB + kwoff + bRow;

    const int plane = sk * 2 + wk;
    const size_t pout_off = (size_t)plane * PT_PLANE + (size_t)nt * 2048 +
                            (size_t)(((wm * 2 + wn) * 32 + lane) * 16);
    const size_t pband_off = (size_t)nt * 2048;
    float* hidA0 = hidden + (size_t)(bA + 0) * NS * NH + h;
    float* hidA1 = hidden + (size_t)(bA + 1) * NS * NH + h;
    float* hidB0 = hidden + (size_t)(bB + 0) * NS * NH + h;
    float* hidB1 = hidden + (size_t)(bB + 1) * NS * NH + h;

    for (int t = 0; t < NS; t++) {
        const int par = t & 1;
        // prefetch update-phase xw operands
        const float2 xA = __ldcs((const float2*)(g_xwn + (size_t)t * BH + (size_t)h * 64 + bA));
        const float2 xB = __ldcs((const float2*)(g_xwn + (size_t)t * BH + (size_t)h * 64 + bB));

        // ===== team A: wait + stage + GEMM + store =====
        if (tid == 0) pollge(&g_cnt[0][sk][0], 32u * (unsigned)t);
        __syncthreads();
        {
            const __half* sig_rd = g_sigh[par];
#pragma unroll
            for (int it = 0; it < 4; it++) {
                const int r = it * 8 + wid;     // team A batch row 0..31
                const uint4* src = (const uint4*)(sig_rd + (size_t)r * NH + kbeg) + lane * 2;
                uint4 v0 = src[0];
                uint4 v1 = src[1];
                *(uint4*)(sm + R_BA + r * PITCH2 + lane * 32) = v0;
                *(uint4*)(sm + R_BA + r * PITCH2 + lane * 32 + 16) = v1;
            }
        }
        __syncthreads();

        float accA[2][2][4];
#pragma unroll
        for (int mi = 0; mi < 2; mi++)
#pragma unroll
            for (int ni = 0; ni < 2; ni++)
#pragma unroll
                for (int j = 0; j < 4; j++) accA[mi][ni][j] = 0.0f;
#pragma unroll 4
        for (int ks = 0; ks < 16; ks++) {
            const uint32_t ko = ks * 32;
            unsigned am[2][4], bm[2][2];
            ldsm4(am[0], aA + ko);
            ldsm4(am[1], aA + 16 * PITCH2 + ko);
            ldsm4(&bm[0][0], bAa + ko);
#pragma unroll
            for (int mi = 0; mi < 2; mi++)
#pragma unroll
                for (int ni = 0; ni < 2; ni++)
                    mma_f16(accA[mi][ni], am[mi], bm[ni]);
        }
        {
            float* pout = g_part[par][0] + pout_off;
#pragma unroll
            for (int qd = 0; qd < 4; qd++)
                *(float4*)(pout + qd * 4) = *(const float4*)accA[qd >> 1][qd & 1];
        }
        cluster_arrive_();   // pA written (release)

        // ===== team B: wait + stage (overlaps pA barrier propagation) =====
        if (tid == 0) pollge(&g_cnt[1][sk][0], 32u * (unsigned)t);
        __syncthreads();
        {
            const __half* sig_rd = g_sigh[par];
#pragma unroll
            for (int it = 0; it < 4; it++) {
                const int r = it * 8 + wid;     // team B batch row 32..63
                const uint4* src = (const uint4*)(sig_rd + (size_t)(r + 32) * NH + kbeg) + lane * 2;
                uint4 v0 = src[0];
                uint4 v1 = src[1];
                *(uint4*)(sm + R_BB + r * PITCH2 + lane * 32) = v0;
                *(uint4*)(sm + R_BB + r * PITCH2 + lane * 32 + 16) = v1;
            }
        }
        __syncthreads();

        cluster_wait_();     // pA visible from all 4 ranks

        // ===== update team A, publish A(t+1) =====
        {
            const float* pb = g_part[par][0] + pband_off;
            float sx = 0.0f, sy = 0.0f;
#pragma unroll
            for (int p = 0; p < 8; p++) {
                float2 s = *(const float2*)(pb + (size_t)p * PT_PLANE + fb);
                sx += s.x;
                sy += s.y;
            }
            float2 v;
            v.x = 0.9f * hpA.x + 0.1f * (sx + xA.x);
            v.y = 0.9f * hpA.y + 0.1f * (sy + xA.y);
            hpA = v;
            __half* sig_wr = g_sigh[par ^ 1];
            sig_wr[(size_t)(bA + 0) * NH + h] = __float2half_rn(sigmoidf_(v.x));
            sig_wr[(size_t)(bA + 1) * NH + h] = __float2half_rn(sigmoidf_(v.y));
        }
        __syncthreads();
        if (tid == 0) arrive(&g_cnt[0][myc][0]);   // sighA(t+1) published

        // ===== team B: GEMM + store + exchange + update =====
        float accB[2][2][4];
#pragma unroll
        for (int mi = 0; mi < 2; mi++)
#pragma unroll
            for (int ni = 0; ni < 2; ni++)
#pragma unroll
                for (int j = 0; j < 4; j++) accB[mi][ni][j] = 0.0f;
#pragma unroll 4
        for (int ks = 0; ks < 16; ks++) {
            const uint32_t ko = ks * 32;
            unsigned am[2][4], bm[2][2];
            ldsm4(am[0], aA + ko);
            ldsm4(am[1], aA + 16 * PITCH2 + ko);
            ldsm4(&bm[0][0], bAb + ko);
#pragma unroll
            for (int mi = 0; mi < 2; mi++)
#pragma unroll
                for (int ni = 0; ni < 2; ni++)
                    mma_f16(accB[mi][ni], am[mi], bm[ni]);
        }
        {
            float* pout = g_part[par][1] + pout_off;
#pragma unroll
            for (int qd = 0; qd < 4; qd++)
                *(float4*)(pout + qd * 4) = *(const float4*)accB[qd >> 1][qd & 1];
        }
        cluster_arrive_();
        cluster_wait_();     // pB visible

        {
            const float* pb = g_part[par][1] + pband_off;
            float sx = 0.0f, sy = 0.0f;
#pragma unroll
            for (int p = 0; p < 8; p++) {
                float2 s = *(const float2*)(pb + (size_t)p * PT_PLANE + fb);
                sx += s.x;
                sy += s.y;
            }
            float2 v;
            v.x = 0.9f * hpB.x + 0.1f * (sx + xB.x);
            v.y = 0.9f * hpB.y + 0.1f * (sy + xB.y);
            hpB = v;
            __half* sig_wr = g_sigh[par ^ 1];
            sig_wr[(size_t)(bB + 0) * NH + h] = __float2half_rn(sigmoidf_(v.x));
            sig_wr[(size_t)(bB + 1) * NH + h] = __float2half_rn(sigmoidf_(v.y));
        }
        __syncthreads();
        if (tid == 0) arrive(&g_cnt[1][myc][0]);   // sighB(t+1) published

        // hidden stores (off critical path; consumed only by k_out)
        __stcs(hidA0 + (size_t)t * NH, hpA.x);
        __stcs(hidA1 + (size_t)t * NH, hpA.y);
        __stcs(hidB0 + (size_t)t * NH, hpB.x);
        __stcs(hidB1 + (size_t)t * NH, hpB.y);
    }

    flag_barrier(0);     // restore flag/slot state
}

// ---------------- k_xw (HMMA): xwn[t][h][b] = x_t @ W_ih^T + 0.1*noise ----------------
__global__ void __launch_bounds__(256)
k_xw(const float* __restrict__ x, const float* __restrict__ noise) {
    extern __shared__ __align__(1024) char sm[];
    const uint32_t smb = smem_u32(sm);
    float* noise_s = (float*)(sm + X_NS);
    const int tid = threadIdx.x;
    const int wid = tid >> 5;
    const int lane = tid & 31;
    const int h0 = blockIdx.x * 128;
    const int t  = blockIdx.y;

    const int warp_m0 = (wid >> 1) * 32;
    const int warp_n0 = (wid & 1) * 32;
    const uint32_t aA = smb + X_W +
        (uint32_t)((warp_m0 + (lane & 15)) * PITCH + ((lane >> 4) << 4));
    const uint32_t bA = smb + X_B +
        (uint32_t)((warp_n0 + (lane & 7) + ((lane >> 4) << 3)) * PITCH +
                   (((lane >> 3) & 1) << 4));

#pragma unroll
    for (int it = 0; it < 8; it++) {
        const int b = it * 8 + wid;
        float4 nv = *(const float4*)(noise + (size_t)t * BH + (size_t)b * NH + h0 + lane * 4);
        *(float4*)(noise_s + b * 132 + lane * 4) = nv;
    }

    float acc[2][4][4];
#pragma unroll
    for (int mi = 0; mi < 2; mi++)
#pragma unroll
        for (int ni = 0; ni < 4; ni++)
#pragma unroll
            for (int j = 0; j < 4; j++) acc[mi][ni][j] = 0.0f;

    for (int c = 0; c < 2; c++) {
        for (int it = 0; it < 16; it++) {
            const int r = it * 8 + wid;
            uint4 hv = *(const uint4*)(g_wih + (size_t)(h0 + r) * NI + c * 256 + lane * 8);
            *(uint4*)(sm + X_W + r * PITCH + lane * 16) = hv;
        }
#pragma unroll
        for (int it = 0; it < 8; it++) {
            const int b = it * 8 + wid;
            const float* xr = x + ((size_t)b * NS + t) * NI + c * 256 + lane * 8;
            float4 v0 = *(const float4*)(xr);
            float4 v1 = *(const float4*)(xr + 4);
            uint4 hv = make_uint4(h2pack(v0.x, v0.y), h2pack(v0.z, v0.w),
                                  h2pack(v1.x, v1.y), h2pack(v1.z, v1.w));
            *(uint4*)(sm + X_B + b * PITCH + lane * 16) = hv;
        }
        __syncthreads();
#pragma unroll 4
        for (int ks = 0; ks < 16; ks++) {
            const uint32_t ko = ks * 32;
            unsigned am[2][4], bm[4][2];
            ldsm4(am[0], aA + ko);
            ldsm4(am[1], aA + ko + 16 * PITCH);
            ldsm4(&bm[0][0], bA + ko);
            ldsm4(&bm[2][0], bA + ko + 16 * PITCH);
#pragma unroll
            for (int mi = 0; mi < 2; mi++)
#pragma unroll
                for (int ni = 0; ni < 4; ni++)
                    mma_f16(acc[mi][ni], am[mi], bm[ni]);
        }
        __syncthreads();
    }

    const int rq = lane >> 2;
    const int cq = (lane & 3) * 2;
#pragma unroll
    for (int mi = 0; mi < 2; mi++) {
        const int hl = warp_m0 + mi * 16 + rq;
#pragma unroll
        for (int ni = 0; ni < 4; ni++) {
            const int b = warp_n0 + ni * 8 + cq;
            float2 v0;
            v0.x = acc[mi][ni][0] + 0.1f * noise_s[(b + 0) * 132 + hl];
            v0.y = acc[mi][ni][1] + 0.1f * noise_s[(b + 1) * 132 + hl];
            *(float2*)(g_xwn + (size_t)t * BH + (size_t)(h0 + hl) * 64 + b) = v0;
            float2 v1;
            v1.x = acc[mi][ni][2] + 0.1f * noise_s[(b + 0) * 132 + hl + 8];
            v1.y = acc[mi][ni][3] + 0.1f * noise_s[(b + 1) * 132 + hl + 8];
            *(float2*)(g_xwn + (size_t)t * BH + (size_t)(h0 + hl + 8) * 64 + b) = v1;
        }
    }
}

// ---------------- k_out (HMMA): out = sigmoid(hidden) @ W_ho^T + b_ho ----------------
__global__ void __launch_bounds__(256)
k_out(const float* __restrict__ hidden, const float* __restrict__ bho,
      float* __restrict__ outp) {
    extern __shared__ __align__(1024) char sm[];
    const uint32_t smb = smem_u32(sm);
    const int tid = threadIdx.x;
    const int wid = tid >> 5;
    const int lane = tid & 31;
    const int o0 = blockIdx.x * 128;
    const int m0 = blockIdx.y * 64;

    const int warp_m0 = (wid >> 1) * 32;
    const int warp_n0 = (wid & 1) * 32;
    const uint32_t aA = smb + O_W +
        (uint32_t)((warp_m0 + (lane & 15)) * PITCH + ((lane >> 4) << 4));
    const uint32_t bA = smb + O_B +
        (uint32_t)((warp_n0 + (lane & 7) + ((lane >> 4) << 3)) * PITCH +
                   (((lane >> 3) & 1) << 4));

    float acc[2][4][4];
#pragma unroll
    for (int mi = 0; mi < 2; mi++)
#pragma unroll
        for (int ni = 0; ni < 4; ni++)
#pragma unroll
            for (int j = 0; j < 4; j++) acc[mi][ni][j] = 0.0f;

    for (int c = 0; c < 8; c++) {
        for (int it = 0; it < 16; it++) {
            const int r = it * 8 + wid;
            uint4 hv = *(const uint4*)(g_who + (size_t)(o0 + r) * NH + c * 256 + lane * 8);
            *(uint4*)(sm + O_W + r * PITCH + lane * 16) = hv;
        }
#pragma unroll
        for (int it = 0; it < 8; it++) {
            const int m = it * 8 + wid;
            const float* hr = hidden + (size_t)(m0 + m) * NH + c * 256 + lane * 8;
            float4 v0 = *(const float4*)(hr);
            float4 v1 = *(const float4*)(hr + 4);
            uint4 hv = make_uint4(
                h2pack(sigmoidf_(v0.x), sigmoidf_(v0.y)),
                h2pack(sigmoidf_(v0.z), sigmoidf_(v0.w)),
                h2pack(sigmoidf_(v1.x), sigmoidf_(v1.y)),
                h2pack(sigmoidf_(v1.z), sigmoidf_(v1.w)));
            *(uint4*)(sm + O_B + m * PITCH + lane * 16) = hv;
        }
        __syncthreads();
#pragma unroll 4
        for (int ks = 0; ks < 16; ks++) {
            const uint32_t ko = ks * 32;
            unsigned am[2][4], bm[4][2];
            ldsm4(am[0], aA + ko);
            ldsm4(am[1], aA + ko + 16 * PITCH);
            ldsm4(&bm[0][0], bA + ko);
            ldsm4(&bm[2][0], bA + ko + 16 * PITCH);
#pragma unroll
            for (int mi = 0; mi < 2; mi++)
#pragma unroll
                for (int ni = 0; ni < 4; ni++)
                    mma_f16(acc[mi][ni], am[mi], bm[ni]);
        }
        __syncthreads();
    }

    const int rq = lane >> 2;
    const int cq = (lane & 3) * 2;
#pragma unroll
    for (int mi = 0; mi < 2; mi++) {
        const int o = o0 + warp_m0 + mi * 16 + rq;
        const float bv0 = bho[o];
        const float bv8 = bho[o + 8];
#pragma unroll
        for (int ni = 0; ni < 4; ni++) {
            const int m = m0 + warp_n0 + ni * 8 + cq;
            outp[(size_t)(m + 0) * NO + o] = acc[mi][ni][0] + bv0;
            outp[(size_t)(m + 1) * NO + o] = acc[mi][ni][1] + bv0;
            outp[(size_t)(m + 0) * NO + o + 8] = acc[mi][ni][2] + bv8;
            outp[(size_t)(m + 1) * NO + o + 8] = acc[mi][ni][3] + bv8;
        }
    }
}

extern "C" void kernel_launch(void* const* d_in, const int* in_sizes, int n_in,
                              void* d_out, int out_size) {
    const float* x     = (const float*)d_in[0];   // [B,S,I]
    const float* h0    = (const float*)d_in[1];   // [B,1,H]
    const float* Wih   = (const float*)d_in[2];   // [H,I]
    const float* Whh   = (const float*)d_in[3];   // [H,H]
    const float* Who   = (const float*)d_in[4];   // [O,H]
    const float* bho   = (const float*)d_in[5];   // [O]
    const float* noise = (const float*)d_in[6];   // [S,B,1,H]
    float* outp = (float*)d_out;

    const size_t OUTE = (size_t)NB * NS * NO;
    const size_t HIDE = (size_t)NB * NS * NH;

    float* hidden;
    if ((size_t)out_size >= OUTE + HIDE) {
        hidden = outp + OUTE;   // harness output = concat(out, hidden)
    } else {
        void* p = nullptr;
        cudaGetSymbolAddress(&p, g_hid_fb);
        hidden = (float*)p;
    }

    cudaFuncSetAttribute(k_recur, cudaFuncAttributeMaxDynamicSharedMemorySize, R_TOTAL);
    cudaFuncSetAttribute(k_xw, cudaFuncAttributeMaxDynamicSharedMemorySize, X_TOTAL);
    cudaFuncSetAttribute(k_out, cudaFuncAttributeMaxDynamicSharedMemorySize, O_TOTAL);

    // 0. one-time weight conversion (fp32 -> fp16)
    k_convW<<<(NH * NI + NO * NH) / 256, 256>>>(Wih, Who);

    // 1. input projection (HMMA) + noise fold, layout [t][h][b]
    k_xw<<<dim3(NH / 128, NS), 256, X_TOTAL>>>(x, noise);

    // 2. full recurrence: persistent HMMA kernel, 4-CTA band clusters,
    //    two-team (batch-split) pipeline hiding counter-propagation latency
    k_recur<<<GB, 256, R_TOTAL>>>(h0, Whh, hidden);

    // 3. output projection (HMMA)
    k_out<<<dim3(NO / 128, (NB * NS) / 64), 256, O_TOTAL>>>(hidden, bho, outp);
}

// round 16
// speedup vs baseline: 1.4483x; 1.4483x over previous
#include <cuda_runtime.h>
#include <cuda_fp16.h>
#include <cstdint>

// ---------------- problem constants ----------------
namespace {
constexpr int NB = 64;     // batch
constexpr int NS = 1024;   // sequence length
constexpr int NI = 512;    // input dim
constexpr int NH = 2048;   // hidden dim
constexpr int NO = 512;    // output dim
constexpr int BH = NB * NH;      // 131072 state elements

constexpr int GB = 128;          // persistent blocks (1/SM, co-resident)
constexpr int SK = 4;            // split-K chunks = cluster size
constexpr int KC = NH / SK;      // 512 K per recurrence block

// k_recur smem: K=512 fp16 rows (1024B) + 16B pad
constexpr int PITCH2 = 1040;
constexpr int R_W = 0;                        // 64 rows (W chunk)
constexpr int R_B = R_W + 64 * PITCH2;        // 64 rows (sigh chunk)
// DSMEM partial exchange buffers: [parity 2][plane 4][1024 floats] = 32 KB
constexpr int P_PART = R_B + 64 * PITCH2;
constexpr int R_TOTAL = P_PART + 2 * 4 * 1024 * 4;   // 165888 B

// projection kernels: K=256 rows (512B) + 16B pad
constexpr int PITCH = 528;
constexpr int X_W  = 0;
constexpr int X_B  = X_W + 128 * PITCH;
constexpr int X_NS = X_B + 64 * PITCH;
constexpr int X_TOTAL = X_NS + 64 * 132 * 4;
constexpr int O_W = 0;
constexpr int O_B = O_W + 128 * PITCH;
constexpr int O_TOTAL = O_B + 64 * PITCH;
}

// ---------------- scratch (static device allocations) ----------------
__device__ float g_xwn[(size_t)NS * NB * NH];     // [t][h][b] xw + 0.1*noise
__device__ float g_hid_fb[(size_t)NB * NS * NH];  // fallback hidden storage
__device__ __half g_sigh[2][BH];                  // ping-pong sigmoid(h) fp16 [b][h]
__device__ __half g_wih[(size_t)NH * NI];         // W_ih fp16 [h][i]
__device__ __half g_who[(size_t)NO * NH];         // W_ho fp16 [o][h]

// sync state
__device__ unsigned g_slots[GB];
__device__ unsigned g_flag;
__device__ unsigned g_cnt[4][8];   // chunk counters (sigh published), 32B-strided

// ---------------- helpers ----------------
__device__ __forceinline__ float sigmoidf_(float x) {
    return 1.0f / (1.0f + __expf(-x));
}
__device__ __forceinline__ unsigned h2pack(float a, float b) {
    __half2 t;
    t.x = __float2half_rn(a);
    t.y = __float2half_rn(b);
    return *reinterpret_cast<unsigned*>(&t);
}
__device__ __forceinline__ uint32_t smem_u32(const void* p) {
    uint32_t a;
    asm("{ .reg .u64 t; cvta.to.shared.u64 t, %1; cvt.u32.u64 %0, t; }"
        : "=r"(a) : "l"(p));
    return a;
}
__device__ __forceinline__ void ldsm4(unsigned* r, uint32_t addr) {
    asm volatile("ldmatrix.sync.aligned.m8n8.x4.shared.b16 {%0,%1,%2,%3}, [%4];"
                 : "=r"(r[0]), "=r"(r[1]), "=r"(r[2]), "=r"(r[3]) : "r"(addr));
}
__device__ __forceinline__ void mma_f16(float* d, const unsigned* a, const unsigned* b) {
    asm("mma.sync.aligned.m16n8k16.row.col.f32.f16.f16.f32 "
        "{%0,%1,%2,%3}, {%4,%5,%6,%7}, {%8,%9}, {%0,%1,%2,%3};"
        : "+f"(d[0]), "+f"(d[1]), "+f"(d[2]), "+f"(d[3])
        : "r"(a[0]), "r"(a[1]), "r"(a[2]), "r"(a[3]), "r"(b[0]), "r"(b[1]));
}

// ---------------- sync primitives ----------------
__device__ __forceinline__ void arrive(unsigned* p) {
    asm volatile("red.release.gpu.global.add.u32 [%0], %1;"
                 :: "l"(p), "r"(1u) : "memory");
}
__device__ __forceinline__ void pollge(unsigned* p, unsigned target) {
    unsigned v;
    do {
        asm volatile("ld.acquire.gpu.global.u32 %0, [%1];"
                     : "=r"(v) : "l"(p) : "memory");
    } while (v < target);
}
__device__ __forceinline__ void cluster_arrive_() {
    asm volatile("barrier.cluster.arrive.aligned;" ::: "memory");
}
__device__ __forceinline__ void cluster_wait_() {
    asm volatile("barrier.cluster.wait.aligned;" ::: "memory");
}
__device__ __forceinline__ uint32_t mapa_(uint32_t addr, uint32_t rank) {
    uint32_t r;
    asm("mapa.shared::cluster.u32 %0, %1, %2;" : "=r"(r) : "r"(addr), "r"(rank));
    return r;
}
__device__ __forceinline__ void st_cluster4(uint32_t addr, const float* v) {
    asm volatile("st.shared::cluster.v4.f32 [%0], {%1,%2,%3,%4};"
                 :: "r"(addr), "f"(v[0]), "f"(v[1]), "f"(v[2]), "f"(v[3])
                 : "memory");
}

// flag-array full barrier (used twice per launch; state returns to 0)
__device__ __forceinline__ void flag_barrier(unsigned want) {
    __syncthreads();
    if (threadIdx.x == 0) {
        asm volatile("st.release.gpu.global.u32 [%0], %1;"
                     :: "l"(&g_slots[blockIdx.x]), "r"(want) : "memory");
    }
    if (blockIdx.x == 0) {
        if (threadIdx.x < GB) {
            unsigned v;
            do {
                asm volatile("ld.acquire.gpu.global.u32 %0, [%1];"
                             : "=r"(v) : "l"(&g_slots[threadIdx.x]) : "memory");
            } while (v != want);
        }
        __syncthreads();
        if (threadIdx.x == 0) {
            asm volatile("st.release.gpu.global.u32 [%0], %1;"
                         :: "l"(&g_flag), "r"(want) : "memory");
        }
    } else {
        if (threadIdx.x == 0) {
            unsigned v;
            do {
                asm volatile("ld.acquire.gpu.global.u32 %0, [%1];"
                             : "=r"(v) : "l"(&g_flag) : "memory");
            } while (v != want);
        }
        __syncthreads();
    }
}

// ---------------- W_ih / W_ho fp32 -> fp16 conversion (one-time) ----------------
__global__ void __launch_bounds__(256) k_convW(const float* __restrict__ Wih,
                                               const float* __restrict__ Who) {
    const int idx = blockIdx.x * 256 + threadIdx.x;
    if (idx < NH * NI) {
        g_wih[idx] = __float2half_rn(Wih[idx]);
    } else {
        int i = idx - NH * NI;
        g_who[i] = __float2half_rn(Who[i]);
    }
}

// ---------------- persistent recurrence kernel (R13 + DSMEM partial exchange) ----------------
// Cluster nt = 4 CTAs (sk=0..3); CTA computes D[64 h, 64 b] over K chunk 512.
// Partials are stored DIRECTLY into the consuming rank's SMEM via mapa +
// st.shared::cluster (parity-buffered, one cluster barrier per step); the
// update phase reads LOCAL SMEM instead of L2.
__global__ void __launch_bounds__(256, 1) __cluster_dims__(SK, 1, 1)
k_recur(const float* __restrict__ h0, const float* __restrict__ Whh,
        float* __restrict__ hidden) {
    extern __shared__ __align__(1024) char sm[];
    const uint32_t smb = smem_u32(sm);
    const int tid = threadIdx.x;
    const int wid = tid >> 5;
    const int lane = tid & 31;
    const int bx = blockIdx.x;
    const int nt = bx >> 2;            // band 0..31 (cluster id)
    const int sk = bx & 3;             // k-chunk / cluster rank
    const int n0 = nt * 64;
    const int kbeg = sk * KC;
    const int myc = nt >> 3;           // chunk this band's sigh feeds

    if (bx == 0 && tid < 4) g_cnt[tid][0] = 0;

    // ---- one-time: stage W_hh chunk [64 rows x 512 k] fp16 into SMEM ----
    for (int it = 0; it < 8; it++) {
        const int r = it * 8 + wid;
        const float* wr = Whh + (size_t)(n0 + r) * NH + kbeg;
#pragma unroll
        for (int g = 0; g < 2; g++) {
            const int c = g * 256 + lane * 8;
            float4 v0 = *(const float4*)(wr + c);
            float4 v1 = *(const float4*)(wr + c + 4);
            uint4 H = make_uint4(h2pack(v0.x, v0.y), h2pack(v0.z, v0.w),
                                 h2pack(v1.x, v1.y), h2pack(v1.z, v1.w));
            *(uint4*)(sm + R_W + r * PITCH2 + c * 2) = H;
        }
    }

    // ---- update mapping (permuted for conflict-free DSMEM layout) ----
    // updater thread u reads quad at byte u*16 of each plane ->
    // slot j = (u&63)*4 + (u>>6); fb = sk*1024 + j*4 (same (h,b) formulas as R13)
    const int j = ((tid & 63) << 2) + (tid >> 6);
    const int fb = (sk << 10) + (j << 2);
    const int w = fb >> 4, q_ = (fb & 15) >> 2;
    const int mi_u = q_ >> 1, ni_u = q_ & 1;
    const int wwid = w >> 5, wlane = w & 31;
    const int hl = ((wwid >> 2) << 5) + mi_u * 16 + (wlane >> 2);
    const int b  = ((wwid & 3) << 4) + ni_u * 8 + ((wlane & 3) << 1);
    const int h  = n0 + hl;   // thread owns (h,b),(h,b+1),(h+8,b),(h+8,b+1)

    // ---- init state: h in registers, sigh[0] fp16 [b][h] ----
    float4 hp;
    hp.x = h0[(size_t)(b + 0) * NH + h];
    hp.y = h0[(size_t)(b + 1) * NH + h];
    hp.z = h0[(size_t)(b + 0) * NH + h + 8];
    hp.w = h0[(size_t)(b + 1) * NH + h + 8];
    g_sigh[0][(size_t)(b + 0) * NH + h] = __float2half_rn(sigmoidf_(hp.x));
    g_sigh[0][(size_t)(b + 1) * NH + h] = __float2half_rn(sigmoidf_(hp.y));
    g_sigh[0][(size_t)(b + 0) * NH + h + 8] = __float2half_rn(sigmoidf_(hp.z));
    g_sigh[0][(size_t)(b + 1) * NH + h + 8] = __float2half_rn(sigmoidf_(hp.w));

    flag_barrier(1);      // counter reset + init sigh visible

    // ---- GEMM constants: warp tile m32 x n16 (R13 layout) ----
    const int warp_m0 = (wid >> 2) << 5;     // 0 / 32
    const int warp_n0 = (wid & 3) << 4;      // 0,16,32,48
    const uint32_t aA = smb + R_W +
        (uint32_t)((warp_m0 + (lane & 15)) * PITCH2 + ((lane >> 4) << 4));
    const uint32_t bA = smb + R_B +
        (uint32_t)((warp_n0 + (lane & 7) + ((lane >> 4) << 3)) * PITCH2 +
                   (((lane >> 3) & 1) << 4));

    // DSMEM epilogue: writer thread tid sends quad qd to rank (tid>>6) at
    // plane sk, byte (qd*64 + (tid&63))*16. mapa base once.
    const uint32_t dst_rank = (uint32_t)(tid >> 6);
    const uint32_t peer_base = mapa_(smb + P_PART, dst_rank) +
                               (uint32_t)(sk * 4096 + (tid & 63) * 16);
    float* hid0 = hidden + (size_t)(b + 0) * NS * NH + h;
    float* hid1 = hidden + (size_t)(b + 1) * NS * NH + h;

    for (int t = 0; t < NS; t++) {
        const int par = t & 1;
        // prefetch update-phase xw operands (hide DRAM latency behind GEMM)
        const float2 x0 = __ldcs((const float2*)(g_xwn + (size_t)t * BH + (size_t)h * 64 + b));
        const float2 x1 = __ldcs((const float2*)(g_xwn + (size_t)t * BH + (size_t)(h + 8) * 64 + b));

        // wait sigh(t) chunk published (32 updater CTAs per chunk)
        if (tid == 0) pollge(&g_cnt[sk][0], 32u * (unsigned)t);
        __syncthreads();

        // stage sigh chunk [64 b rows x 512 k] fp16 into SMEM (buffer t&1)
        const __half* sig_rd = g_sigh[par];
#pragma unroll
        for (int it = 0; it < 8; it++) {
            const int r = it * 8 + wid;
            const uint4* src = (const uint4*)(sig_rd + (size_t)r * NH + kbeg) + lane * 2;
            uint4 v0 = src[0];
            uint4 v1 = src[1];
            *(uint4*)(sm + R_B + r * PITCH2 + lane * 32) = v0;
            *(uint4*)(sm + R_B + r * PITCH2 + lane * 32 + 16) = v1;
        }
        __syncthreads();

        // GEMM m64n64k512: 32 k-steps x (3 ldsm4 + 4 MMA)
        float acc[2][2][4];
#pragma unroll
        for (int mi = 0; mi < 2; mi++)
#pragma unroll
            for (int ni = 0; ni < 2; ni++)
#pragma unroll
                for (int j2 = 0; j2 < 4; j2++) acc[mi][ni][j2] = 0.0f;

#pragma unroll 4
        for (int ks = 0; ks < 32; ks++) {
            const uint32_t ko = ks * 32;
            unsigned am[2][4], bm[2][2];
            ldsm4(am[0], aA + ko);
            ldsm4(am[1], aA + 16 * PITCH2 + ko);
            ldsm4(&bm[0][0], bA + ko);
#pragma unroll
            for (int mi = 0; mi < 2; mi++)
#pragma unroll
                for (int ni = 0; ni < 2; ni++)
                    mma_f16(acc[mi][ni], am[mi], bm[ni]);
        }

        // store partials straight into the consuming rank's SMEM (parity buf)
        {
            const uint32_t pb = peer_base + (uint32_t)(par * 16384);
#pragma unroll
            for (int qd = 0; qd < 4; qd++)
                st_cluster4(pb + (uint32_t)(qd * 1024), acc[qd >> 1][qd & 1]);
        }

        cluster_arrive_();   // partials written (release)
        cluster_wait_();     // all 4 ranks' partials in local SMEM (acquire)

        // read partials from LOCAL SMEM (planes 0..3, conflict-free)
        const char* pbase = sm + P_PART + par * 16384 + tid * 16;
        float4 s0 = *(const float4*)(pbase);
        float4 s1 = *(const float4*)(pbase + 4096);
        float4 s2 = *(const float4*)(pbase + 8192);
        float4 s3 = *(const float4*)(pbase + 12288);

        // fused Euler update
        float4 v;
        v.x = 0.9f * hp.x + 0.1f * (s0.x + s1.x + s2.x + s3.x + x0.x);
        v.y = 0.9f * hp.y + 0.1f * (s0.y + s1.y + s2.y + s3.y + x0.y);
        v.z = 0.9f * hp.z + 0.1f * (s0.z + s1.z + s2.z + s3.z + x1.x);
        v.w = 0.9f * hp.w + 0.1f * (s0.w + s1.w + s2.w + s3.w + x1.y);
        hp = v;

        // write sigh(t+1) into the OTHER buffer
        __half* sig_wr = g_sigh[par ^ 1];
        sig_wr[(size_t)(b + 0) * NH + h] = __float2half_rn(sigmoidf_(v.x));
        sig_wr[(size_t)(b + 1) * NH + h] = __float2half_rn(sigmoidf_(v.y));
        sig_wr[(size_t)(b + 0) * NH + h + 8] = __float2half_rn(sigmoidf_(v.z));
        sig_wr[(size_t)(b + 1) * NH + h + 8] = __float2half_rn(sigmoidf_(v.w));
        __syncthreads();
        if (tid == 0) arrive(&g_cnt[myc][0]);  // sigh(t+1) published

        // hidden stores (off critical path; consumed only by k_out)
        __stcs(hid0 + (size_t)t * NH, v.x);
        __stcs(hid1 + (size_t)t * NH, v.y);
        __stcs(hid0 + (size_t)t * NH + 8, v.z);
        __stcs(hid1 + (size_t)t * NH + 8, v.w);
    }

    flag_barrier(0);     // restore flag/slot state
}

// ---------------- k_xw (HMMA): xwn[t][h][b] = x_t @ W_ih^T + 0.1*noise ----------------
__global__ void __launch_bounds__(256)
k_xw(const float* __restrict__ x, const float* __restrict__ noise) {
    extern __shared__ __align__(1024) char sm[];
    const uint32_t smb = smem_u32(sm);
    float* noise_s = (float*)(sm + X_NS);
    const int tid = threadIdx.x;
    const int wid = tid >> 5;
    const int lane = tid & 31;
    const int h0 = blockIdx.x * 128;
    const int t  = blockIdx.y;

    const int warp_m0 = (wid >> 1) * 32;
    const int warp_n0 = (wid & 1) * 32;
    const uint32_t aA = smb + X_W +
        (uint32_t)((warp_m0 + (lane & 15)) * PITCH + ((lane >> 4) << 4));
    const uint32_t bA = smb + X_B +
        (uint32_t)((warp_n0 + (lane & 7) + ((lane >> 4) << 3)) * PITCH +
                   (((lane >> 3) & 1) << 4));

#pragma unroll
    for (int it = 0; it < 8; it++) {
        const int b = it * 8 + wid;
        float4 nv = *(const float4*)(noise + (size_t)t * BH + (size_t)b * NH + h0 + lane * 4);
        *(float4*)(noise_s + b * 132 + lane * 4) = nv;
    }

    float acc[2][4][4];
#pragma unroll
    for (int mi = 0; mi < 2; mi++)
#pragma unroll
        for (int ni = 0; ni < 4; ni++)
#pragma unroll
            for (int j = 0; j < 4; j++) acc[mi][ni][j] = 0.0f;

    for (int c = 0; c < 2; c++) {
        for (int it = 0; it < 16; it++) {
            const int r = it * 8 + wid;
            uint4 hv = *(const uint4*)(g_wih + (size_t)(h0 + r) * NI + c * 256 + lane * 8);
            *(uint4*)(sm + X_W + r * PITCH + lane * 16) = hv;
        }
#pragma unroll
        for (int it = 0; it < 8; it++) {
            const int b = it * 8 + wid;
            const float* xr = x + ((size_t)b * NS + t) * NI + c * 256 + lane * 8;
            float4 v0 = *(const float4*)(xr);
            float4 v1 = *(const float4*)(xr + 4);
            uint4 hv = make_uint4(h2pack(v0.x, v0.y), h2pack(v0.z, v0.w),
                                  h2pack(v1.x, v1.y), h2pack(v1.z, v1.w));
            *(uint4*)(sm + X_B + b * PITCH + lane * 16) = hv;
        }
        __syncthreads();
#pragma unroll 4
        for (int ks = 0; ks < 16; ks++) {
            const uint32_t ko = ks * 32;
            unsigned am[2][4], bm[4][2];
            ldsm4(am[0], aA + ko);
            ldsm4(am[1], aA + ko + 16 * PITCH);
            ldsm4(&bm[0][0], bA + ko);
            ldsm4(&bm[2][0], bA + ko + 16 * PITCH);
#pragma unroll
            for (int mi = 0; mi < 2; mi++)
#pragma unroll
                for (int ni = 0; ni < 4; ni++)
                    mma_f16(acc[mi][ni], am[mi], bm[ni]);
        }
        __syncthreads();
    }

    const int rq = lane >> 2;
    const int cq = (lane & 3) * 2;
#pragma unroll
    for (int mi = 0; mi < 2; mi++) {
        const int hl = warp_m0 + mi * 16 + rq;
#pragma unroll
        for (int ni = 0; ni < 4; ni++) {
            const int b = warp_n0 + ni * 8 + cq;
            float2 v0;
            v0.x = acc[mi][ni][0] + 0.1f * noise_s[(b + 0) * 132 + hl];
            v0.y = acc[mi][ni][1] + 0.1f * noise_s[(b + 1) * 132 + hl];
            *(float2*)(g_xwn + (size_t)t * BH + (size_t)(h0 + hl) * 64 + b) = v0;
            float2 v1;
            v1.x = acc[mi][ni][2] + 0.1f * noise_s[(b + 0) * 132 + hl + 8];
            v1.y = acc[mi][ni][3] + 0.1f * noise_s[(b + 1) * 132 + hl + 8];
            *(float2*)(g_xwn + (size_t)t * BH + (size_t)(h0 + hl + 8) * 64 + b) = v1;
        }
    }
}

// ---------------- k_out (HMMA): out = sigmoid(hidden) @ W_ho^T + b_ho ----------------
__global__ void __launch_bounds__(256)
k_out(const float* __restrict__ hidden, const float* __restrict__ bho,
      float* __restrict__ outp) {
    extern __shared__ __align__(1024) char sm[];
    const uint32_t smb = smem_u32(sm);
    const int tid = threadIdx.x;
    const int wid = tid >> 5;
    const int lane = tid & 31;
    const int o0 = blockIdx.x * 128;
    const int m0 = blockIdx.y * 64;

    const int warp_m0 = (wid >> 1) * 32;
    const int warp_n0 = (wid & 1) * 32;
    const uint32_t aA = smb + O_W +
        (uint32_t)((warp_m0 + (lane & 15)) * PITCH + ((lane >> 4) << 4));
    const uint32_t bA = smb + O_B +
        (uint32_t)((warp_n0 + (lane & 7) + ((lane >> 4) << 3)) * PITCH +
                   (((lane >> 3) & 1) << 4));

    float acc[2][4][4];
#pragma unroll
    for (int mi = 0; mi < 2; mi++)
#pragma unroll
        for (int ni = 0; ni < 4; ni++)
#pragma unroll
            for (int j = 0; j < 4; j++) acc[mi][ni][j] = 0.0f;

    for (int c = 0; c < 8; c++) {
        for (int it = 0; it < 16; it++) {
            const int r = it * 8 + wid;
            uint4 hv = *(const uint4*)(g_who + (size_t)(o0 + r) * NH + c * 256 + lane * 8);
            *(uint4*)(sm + O_W + r * PITCH + lane * 16) = hv;
        }
#pragma unroll
        for (int it = 0; it < 8; it++) {
            const int m = it * 8 + wid;
            const float* hr = hidden + (size_t)(m0 + m) * NH + c * 256 + lane * 8;
            float4 v0 = *(const float4*)(hr);
            float4 v1 = *(const float4*)(hr + 4);
            uint4 hv = make_uint4(
                h2pack(sigmoidf_(v0.x), sigmoidf_(v0.y)),
                h2pack(sigmoidf_(v0.z), sigmoidf_(v0.w)),
                h2pack(sigmoidf_(v1.x), sigmoidf_(v1.y)),
                h2pack(sigmoidf_(v1.z), sigmoidf_(v1.w)));
            *(uint4*)(sm + O_B + m * PITCH + lane * 16) = hv;
        }
        __syncthreads();
#pragma unroll 4
        for (int ks = 0; ks < 16; ks++) {
            const uint32_t ko = ks * 32;
            unsigned am[2][4], bm[4][2];
            ldsm4(am[0], aA + ko);
            ldsm4(am[1], aA + ko + 16 * PITCH);
            ldsm4(&bm[0][0], bA + ko);
            ldsm4(&bm[2][0], bA + ko + 16 * PITCH);
#pragma unroll
            for (int mi = 0; mi < 2; mi++)
#pragma unroll
                for (int ni = 0; ni < 4; ni++)
                    mma_f16(acc[mi][ni], am[mi], bm[ni]);
        }
        __syncthreads();
    }

    const int rq = lane >> 2;
    const int cq = (lane & 3) * 2;
#pragma unroll
    for (int mi = 0; mi < 2; mi++) {
        const int o = o0 + warp_m0 + mi * 16 + rq;
        const float bv0 = bho[o];
        const float bv8 = bho[o + 8];
#pragma unroll
        for (int ni = 0; ni < 4; ni++) {
            const int m = m0 + warp_n0 + ni * 8 + cq;
            outp[(size_t)(m + 0) * NO + o] = acc[mi][ni][0] + bv0;
            outp[(size_t)(m + 1) * NO + o] = acc[mi][ni][1] + bv0;
            outp[(size_t)(m + 0) * NO + o + 8] = acc[mi][ni][2] + bv8;
            outp[(size_t)(m + 1) * NO + o + 8] = acc[mi][ni][3] + bv8;
        }
    }
}

extern "C" void kernel_launch(void* const* d_in, const int* in_sizes, int n_in,
                              void* d_out, int out_size) {
    const float* x     = (const float*)d_in[0];   // [B,S,I]
    const float* h0    = (const float*)d_in[1];   // [B,1,H]
    const float* Wih   = (const float*)d_in[2];   // [H,I]
    const float* Whh   = (const float*)d_in[3];   // [H,H]
    const float* Who   = (const float*)d_in[4];   // [O,H]
    const float* bho   = (const float*)d_in[5];   // [O]
    const float* noise = (const float*)d_in[6];   // [S,B,1,H]
    float* outp = (float*)d_out;

    const size_t OUTE = (size_t)NB * NS * NO;
    const size_t HIDE = (size_t)NB * NS * NH;

    float* hidden;
    if ((size_t)out_size >= OUTE + HIDE) {
        hidden = outp + OUTE;   // harness output = concat(out, hidden)
    } else {
        void* p = nullptr;
        cudaGetSymbolAddress(&p, g_hid_fb);
        hidden = (float*)p;
    }

    cudaFuncSetAttribute(k_recur, cudaFuncAttributeMaxDynamicSharedMemorySize, R_TOTAL);
    cudaFuncSetAttribute(k_xw, cudaFuncAttributeMaxDynamicSharedMemorySize, X_TOTAL);
    cudaFuncSetAttribute(k_out, cudaFuncAttributeMaxDynamicSharedMemorySize, O_TOTAL);

    // 0. one-time weight conversion (fp32 -> fp16)
    k_convW<<<(NH * NI + NO * NH) / 256, 256>>>(Wih, Who);

    // 1. input projection (HMMA) + noise fold, layout [t][h][b]
    k_xw<<<dim3(NH / 128, NS), 256, X_TOTAL>>>(x, noise);

    // 2. full recurrence: persistent HMMA kernel, 4-CTA band clusters,
    //    DSMEM partial exchange (update reads local SMEM, not L2)
    k_recur<<<GB, 256, R_TOTAL>>>(h0, Whh, hidden);

    // 3. output projection (HMMA)
    k_out<<<dim3(NO / 128, (NB * NS) / 64), 256, O_TOTAL>>>(hidden, bho, outp);
}

// round 17
// speedup vs baseline: 1.5506x; 1.0706x over previous
#include <cuda_runtime.h>
#include <cuda_fp16.h>
#include <cstdint>

// ---------------- problem constants ----------------
namespace {
constexpr int NB = 64;     // batch
constexpr int NS = 1024;   // sequence length
constexpr int NI = 512;    // input dim
constexpr int NH = 2048;   // hidden dim
constexpr int NO = 512;    // output dim
constexpr int BH = NB * NH;      // 131072 state elements

constexpr int GB = 128;          // persistent blocks (1/SM, co-resident)
constexpr int SK = 4;            // split-K chunks = cluster size
constexpr int KC = NH / SK;      // 512 K per recurrence block

// k_recur smem:
//  W tile: 64 rows x 1024B (512 fp16) + 16B pad
constexpr int PITCH2 = 1040;
//  B (sigh) tile: [k][b] 512 rows x 128B + 16B pad (conflict-free ldmatrix.trans)
constexpr int PITCHB = 144;
constexpr int R_W = 0;                         // 64 rows (W chunk)
constexpr int R_B = R_W + 64 * PITCH2;         // 512 k-rows (sigh chunk, [k][b])
constexpr int P_PART = R_B + 512 * PITCHB;     // DSMEM partials [par2][plane4][1024 f]
constexpr int R_TOTAL = P_PART + 2 * 4 * 1024 * 4;   // 173056 B

// projection kernels: K=256 rows (512B) + 16B pad
constexpr int PITCH = 528;
constexpr int X_W  = 0;
constexpr int X_B  = X_W + 128 * PITCH;
constexpr int X_NS = X_B + 64 * PITCH;
constexpr int X_TOTAL = X_NS + 64 * 132 * 4;
constexpr int O_W = 0;
constexpr int O_B = O_W + 128 * PITCH;
constexpr int O_TOTAL = O_B + 64 * PITCH;
}

// ---------------- scratch (static device allocations) ----------------
__device__ float g_xwn[(size_t)NS * NB * NH];     // [t][h][b] xw + 0.1*noise
__device__ float g_hid_fb[(size_t)NB * NS * NH];  // fallback hidden storage
__device__ __half g_sigh[2][BH];                  // ping-pong sigmoid(h) fp16 [h][b]
__device__ __half g_wih[(size_t)NH * NI];         // W_ih fp16 [h][i]
__device__ __half g_who[(size_t)NO * NH];         // W_ho fp16 [o][h]

// sync state
__device__ unsigned g_slots[GB];
__device__ unsigned g_flag;
__device__ unsigned g_cnt[4][8];   // chunk counters (sigh published), 32B-strided

// ---------------- helpers ----------------
__device__ __forceinline__ float sigmoidf_(float x) {
    return 1.0f / (1.0f + __expf(-x));
}
__device__ __forceinline__ unsigned h2pack(float a, float b) {
    __half2 t;
    t.x = __float2half_rn(a);
    t.y = __float2half_rn(b);
    return *reinterpret_cast<unsigned*>(&t);
}
__device__ __forceinline__ uint32_t smem_u32(const void* p) {
    uint32_t a;
    asm("{ .reg .u64 t; cvta.to.shared.u64 t, %1; cvt.u32.u64 %0, t; }"
        : "=r"(a) : "l"(p));
    return a;
}
__device__ __forceinline__ void ldsm4(unsigned* r, uint32_t addr) {
    asm volatile("ldmatrix.sync.aligned.m8n8.x4.shared.b16 {%0,%1,%2,%3}, [%4];"
                 : "=r"(r[0]), "=r"(r[1]), "=r"(r[2]), "=r"(r[3]) : "r"(addr));
}
__device__ __forceinline__ void ldsm4t(unsigned* r, uint32_t addr) {
    asm volatile("ldmatrix.sync.aligned.m8n8.x4.trans.shared.b16 {%0,%1,%2,%3}, [%4];"
                 : "=r"(r[0]), "=r"(r[1]), "=r"(r[2]), "=r"(r[3]) : "r"(addr));
}
__device__ __forceinline__ void mma_f16(float* d, const unsigned* a, const unsigned* b) {
    asm("mma.sync.aligned.m16n8k16.row.col.f32.f16.f16.f32 "
        "{%0,%1,%2,%3}, {%4,%5,%6,%7}, {%8,%9}, {%0,%1,%2,%3};"
        : "+f"(d[0]), "+f"(d[1]), "+f"(d[2]), "+f"(d[3])
        : "r"(a[0]), "r"(a[1]), "r"(a[2]), "r"(a[3]), "r"(b[0]), "r"(b[1]));
}

// ---------------- sync primitives ----------------
__device__ __forceinline__ void arrive(unsigned* p) {
    asm volatile("red.release.gpu.global.add.u32 [%0], %1;"
                 :: "l"(p), "r"(1u) : "memory");
}
__device__ __forceinline__ void pollge(unsigned* p, unsigned target) {
    unsigned v;
    do {
        asm volatile("ld.acquire.gpu.global.u32 %0, [%1];"
                     : "=r"(v) : "l"(p) : "memory");
    } while (v < target);
}
__device__ __forceinline__ void cluster_arrive_() {
    asm volatile("barrier.cluster.arrive.aligned;" ::: "memory");
}
__device__ __forceinline__ void cluster_wait_() {
    asm volatile("barrier.cluster.wait.aligned;" ::: "memory");
}
__device__ __forceinline__ uint32_t mapa_(uint32_t addr, uint32_t rank) {
    uint32_t r;
    asm("mapa.shared::cluster.u32 %0, %1, %2;" : "=r"(r) : "r"(addr), "r"(rank));
    return r;
}
__device__ __forceinline__ void st_cluster4(uint32_t addr, const float* v) {
    asm volatile("st.shared::cluster.v4.f32 [%0], {%1,%2,%3,%4};"
                 :: "r"(addr), "f"(v[0]), "f"(v[1]), "f"(v[2]), "f"(v[3])
                 : "memory");
}

// flag-array full barrier (used twice per launch; state returns to 0)
__device__ __forceinline__ void flag_barrier(unsigned want) {
    __syncthreads();
    if (threadIdx.x == 0) {
        asm volatile("st.release.gpu.global.u32 [%0], %1;"
                     :: "l"(&g_slots[blockIdx.x]), "r"(want) : "memory");
    }
    if (blockIdx.x == 0) {
        if (threadIdx.x < GB) {
            unsigned v;
            do {
                asm volatile("ld.acquire.gpu.global.u32 %0, [%1];"
                             : "=r"(v) : "l"(&g_slots[threadIdx.x]) : "memory");
            } while (v != want);
        }
        __syncthreads();
        if (threadIdx.x == 0) {
            asm volatile("st.release.gpu.global.u32 [%0], %1;"
                         :: "l"(&g_flag), "r"(want) : "memory");
        }
    } else {
        if (threadIdx.x == 0) {
            unsigned v;
            do {
                asm volatile("ld.acquire.gpu.global.u32 %0, [%1];"
                             : "=r"(v) : "l"(&g_flag) : "memory");
            } while (v != want);
        }
        __syncthreads();
    }
}

// ---------------- W_ih / W_ho fp32 -> fp16 conversion (one-time) ----------------
__global__ void __launch_bounds__(256) k_convW(const float* __restrict__ Wih,
                                               const float* __restrict__ Who) {
    const int idx = blockIdx.x * 256 + threadIdx.x;
    if (idx < NH * NI) {
        g_wih[idx] = __float2half_rn(Wih[idx]);
    } else {
        int i = idx - NH * NI;
        g_who[i] = __float2half_rn(Who[i]);
    }
}

// ---------------- persistent recurrence kernel ----------------
// R16 + transposed sigh ([h][b] global, [k][b] SMEM + ldmatrix.trans):
// coalesced sigh publish (2x 4B stores/thread) and contiguous staging rows.
__global__ void __launch_bounds__(256, 1) __cluster_dims__(SK, 1, 1)
k_recur(const float* __restrict__ h0, const float* __restrict__ Whh,
        float* __restrict__ hidden) {
    extern __shared__ __align__(1024) char sm[];
    const uint32_t smb = smem_u32(sm);
    const int tid = threadIdx.x;
    const int wid = tid >> 5;
    const int lane = tid & 31;
    const int bx = blockIdx.x;
    const int nt = bx >> 2;            // band 0..31 (cluster id)
    const int sk = bx & 3;             // k-chunk / cluster rank
    const int n0 = nt * 64;
    const int kbeg = sk * KC;
    const int myc = nt >> 3;           // chunk this band's sigh feeds

    if (bx == 0 && tid < 4) g_cnt[tid][0] = 0;

    // ---- one-time: stage W_hh chunk [64 rows x 512 k] fp16 into SMEM ----
    for (int it = 0; it < 8; it++) {
        const int r = it * 8 + wid;
        const float* wr = Whh + (size_t)(n0 + r) * NH + kbeg;
#pragma unroll
        for (int g = 0; g < 2; g++) {
            const int c = g * 256 + lane * 8;
            float4 v0 = *(const float4*)(wr + c);
            float4 v1 = *(const float4*)(wr + c + 4);
            uint4 H = make_uint4(h2pack(v0.x, v0.y), h2pack(v0.z, v0.w),
                                 h2pack(v1.x, v1.y), h2pack(v1.z, v1.w));
            *(uint4*)(sm + R_W + r * PITCH2 + c * 2) = H;
        }
    }

    // ---- update mapping (permuted for conflict-free DSMEM layout, as R16) ----
    const int j = ((tid & 63) << 2) + (tid >> 6);
    const int fb = (sk << 10) + (j << 2);
    const int w = fb >> 4, q_ = (fb & 15) >> 2;
    const int mi_u = q_ >> 1, ni_u = q_ & 1;
    const int wwid = w >> 5, wlane = w & 31;
    const int hl = ((wwid >> 2) << 5) + mi_u * 16 + (wlane >> 2);
    const int b  = ((wwid & 3) << 4) + ni_u * 8 + ((wlane & 3) << 1);
    const int h  = n0 + hl;   // thread owns (h,b),(h,b+1),(h+8,b),(h+8,b+1)

    // ---- init state: h in registers, sigh[0] fp16 [h][b] (coalesced u32) ----
    float4 hp;
    hp.x = h0[(size_t)(b + 0) * NH + h];
    hp.y = h0[(size_t)(b + 1) * NH + h];
    hp.z = h0[(size_t)(b + 0) * NH + h + 8];
    hp.w = h0[(size_t)(b + 1) * NH + h + 8];
    *(unsigned*)((__half*)g_sigh[0] + (size_t)h * 64 + b) =
        h2pack(sigmoidf_(hp.x), sigmoidf_(hp.y));
    *(unsigned*)((__half*)g_sigh[0] + (size_t)(h + 8) * 64 + b) =
        h2pack(sigmoidf_(hp.z), sigmoidf_(hp.w));

    flag_barrier(1);      // counter reset + init sigh visible

    // ---- GEMM constants ----
    // A (W): warp tile m32 (warp_m0), k via ko; unchanged from R16.
    const int warp_m0 = (wid >> 2) << 5;     // 0 / 32
    const int warp_n0 = (wid & 3) << 4;      // 0,16,32,48
    const uint32_t aA = smb + R_W +
        (uint32_t)((warp_m0 + (lane & 15)) * PITCH2 + ((lane >> 4) << 4));
    // B (sigh): SMEM [k][b] rows; ldmatrix.trans address:
    // row = (lane&7) + ((lane>>3)&1)*8 (+16 per k-step), col = warp_n0*2 + ((lane>>4)&1)*16
    const uint32_t bAt = smb + R_B +
        (uint32_t)(((lane & 7) + (((lane >> 3) & 1) << 3)) * PITCHB +
                   warp_n0 * 2 + (((lane >> 4) & 1) << 4));

    // DSMEM epilogue (unchanged from R16)
    const uint32_t dst_rank = (uint32_t)(tid >> 6);
    const uint32_t peer_base = mapa_(smb + P_PART, dst_rank) +
                               (uint32_t)(sk * 4096 + (tid & 63) * 16);
    float* hid0 = hidden + (size_t)(b + 0) * NS * NH + h;
    float* hid1 = hidden + (size_t)(b + 1) * NS * NH + h;

    for (int t = 0; t < NS; t++) {
        const int par = t & 1;
        // prefetch update-phase xw operands (hide DRAM latency behind GEMM)
        const float2 x0 = __ldcs((const float2*)(g_xwn + (size_t)t * BH + (size_t)h * 64 + b));
        const float2 x1 = __ldcs((const float2*)(g_xwn + (size_t)t * BH + (size_t)(h + 8) * 64 + b));

        // wait sigh(t) chunk published (32 updater CTAs per chunk)
        if (tid == 0) pollge(&g_cnt[sk][0], 32u * (unsigned)t);
        __syncthreads();

        // stage sigh chunk [512 k-rows x 64 b] fp16 into SMEM [k][b]
        // (global rows are contiguous 128B; fully coalesced)
        {
            const __half* sig_rd = g_sigh[par] + (size_t)kbeg * 64;
            const int rr = tid >> 3;            // 0..31
            const int cc = (tid & 7) * 8;       // halves
#pragma unroll
            for (int it = 0; it < 16; it++) {
                const int r = it * 32 + rr;
                uint4 v = *(const uint4*)(sig_rd + (size_t)r * 64 + cc);
                *(uint4*)(sm + R_B + r * PITCHB + cc * 2) = v;
            }
        }
        __syncthreads();

        // GEMM m64n64k512: 32 k-steps x (2 ldsm4 + 1 ldsm4t + 4 MMA)
        float acc[2][2][4];
#pragma unroll
        for (int mi = 0; mi < 2; mi++)
#pragma unroll
            for (int ni = 0; ni < 2; ni++)
#pragma unroll
                for (int j2 = 0; j2 < 4; j2++) acc[mi][ni][j2] = 0.0f;

#pragma unroll 4
        for (int ks = 0; ks < 32; ks++) {
            const uint32_t ko = ks * 32;            // A: 16 halves = 32B
            unsigned am[2][4], bm[2][2];
            ldsm4(am[0], aA + ko);
            ldsm4(am[1], aA + 16 * PITCH2 + ko);
            ldsm4t(&bm[0][0], bAt + (uint32_t)(ks * 16 * PITCHB));
#pragma unroll
            for (int mi = 0; mi < 2; mi++)
#pragma unroll
                for (int ni = 0; ni < 2; ni++)
                    mma_f16(acc[mi][ni], am[mi], bm[ni]);
        }

        // store partials straight into the consuming rank's SMEM (parity buf)
        {
            const uint32_t pb = peer_base + (uint32_t)(par * 16384);
#pragma unroll
            for (int qd = 0; qd < 4; qd++)
                st_cluster4(pb + (uint32_t)(qd * 1024), acc[qd >> 1][qd & 1]);
        }

        cluster_arrive_();   // partials written (release)
        cluster_wait_();     // all 4 ranks' partials in local SMEM (acquire)

        // read partials from LOCAL SMEM (planes 0..3, conflict-free)
        const char* pbase = sm + P_PART + par * 16384 + tid * 16;
        float4 s0 = *(const float4*)(pbase);
        float4 s1 = *(const float4*)(pbase + 4096);
        float4 s2 = *(const float4*)(pbase + 8192);
        float4 s3 = *(const float4*)(pbase + 12288);

        // fused Euler update
        float4 v;
        v.x = 0.9f * hp.x + 0.1f * (s0.x + s1.x + s2.x + s3.x + x0.x);
        v.y = 0.9f * hp.y + 0.1f * (s0.y + s1.y + s2.y + s3.y + x0.y);
        v.z = 0.9f * hp.z + 0.1f * (s0.z + s1.z + s2.z + s3.z + x1.x);
        v.w = 0.9f * hp.w + 0.1f * (s0.w + s1.w + s2.w + s3.w + x1.y);
        hp = v;

        // write sigh(t+1) into the OTHER buffer ([h][b]: 2 coalesced u32 stores)
        __half* sig_wr = (__half*)g_sigh[par ^ 1];
        *(unsigned*)(sig_wr + (size_t)h * 64 + b) = h2pack(sigmoidf_(v.x), sigmoidf_(v.y));
        *(unsigned*)(sig_wr + (size_t)(h + 8) * 64 + b) = h2pack(sigmoidf_(v.z), sigmoidf_(v.w));
        __syncthreads();
        if (tid == 0) arrive(&g_cnt[myc][0]);  // sigh(t+1) published

        // hidden stores (off critical path; consumed only by k_out)
        __stcs(hid0 + (size_t)t * NH, v.x);
        __stcs(hid1 + (size_t)t * NH, v.y);
        __stcs(hid0 + (size_t)t * NH + 8, v.z);
        __stcs(hid1 + (size_t)t * NH + 8, v.w);
    }

    flag_barrier(0);     // restore flag/slot state
}

// ---------------- k_xw (HMMA): xwn[t][h][b] = x_t @ W_ih^T + 0.1*noise ----------------
__global__ void __launch_bounds__(256)
k_xw(const float* __restrict__ x, const float* __restrict__ noise) {
    extern __shared__ __align__(1024) char sm[];
    const uint32_t smb = smem_u32(sm);
    float* noise_s = (float*)(sm + X_NS);
    const int tid = threadIdx.x;
    const int wid = tid >> 5;
    const int lane = tid & 31;
    const int h0 = blockIdx.x * 128;
    const int t  = blockIdx.y;

    const int warp_m0 = (wid >> 1) * 32;
    const int warp_n0 = (wid & 1) * 32;
    const uint32_t aA = smb + X_W +
        (uint32_t)((warp_m0 + (lane & 15)) * PITCH + ((lane >> 4) << 4));
    const uint32_t bA = smb + X_B +
        (uint32_t)((warp_n0 + (lane & 7) + ((lane >> 4) << 3)) * PITCH +
                   (((lane >> 3) & 1) << 4));

#pragma unroll
    for (int it = 0; it < 8; it++) {
        const int b = it * 8 + wid;
        float4 nv = *(const float4*)(noise + (size_t)t * BH + (size_t)b * NH + h0 + lane * 4);
        *(float4*)(noise_s + b * 132 + lane * 4) = nv;
    }

    float acc[2][4][4];
#pragma unroll
    for (int mi = 0; mi < 2; mi++)
#pragma unroll
        for (int ni = 0; ni < 4; ni++)
#pragma unroll
            for (int j = 0; j < 4; j++) acc[mi][ni][j] = 0.0f;

    for (int c = 0; c < 2; c++) {
        for (int it = 0; it < 16; it++) {
            const int r = it * 8 + wid;
            uint4 hv = *(const uint4*)(g_wih + (size_t)(h0 + r) * NI + c * 256 + lane * 8);
            *(uint4*)(sm + X_W + r * PITCH + lane * 16) = hv;
        }
#pragma unroll
        for (int it = 0; it < 8; it++) {
            const int b = it * 8 + wid;
            const float* xr = x + ((size_t)b * NS + t) * NI + c * 256 + lane * 8;
            float4 v0 = *(const float4*)(xr);
            float4 v1 = *(const float4*)(xr + 4);
            uint4 hv = make_uint4(h2pack(v0.x, v0.y), h2pack(v0.z, v0.w),
                                  h2pack(v1.x, v1.y), h2pack(v1.z, v1.w));
            *(uint4*)(sm + X_B + b * PITCH + lane * 16) = hv;
        }
        __syncthreads();
#pragma unroll 4
        for (int ks = 0; ks < 16; ks++) {
            const uint32_t ko = ks * 32;
            unsigned am[2][4], bm[4][2];
            ldsm4(am[0], aA + ko);
            ldsm4(am[1], aA + ko + 16 * PITCH);
            ldsm4(&bm[0][0], bA + ko);
            ldsm4(&bm[2][0], bA + ko + 16 * PITCH);
#pragma unroll
            for (int mi = 0; mi < 2; mi++)
#pragma unroll
                for (int ni = 0; ni < 4; ni++)
                    mma_f16(acc[mi][ni], am[mi], bm[ni]);
        }
        __syncthreads();
    }

    const int rq = lane >> 2;
    const int cq = (lane & 3) * 2;
#pragma unroll
    for (int mi = 0; mi < 2; mi++) {
        const int hl = warp_m0 + mi * 16 + rq;
#pragma unroll
        for (int ni = 0; ni < 4; ni++) {
            const int b = warp_n0 + ni * 8 + cq;
            float2 v0;
            v0.x = acc[mi][ni][0] + 0.1f * noise_s[(b + 0) * 132 + hl];
            v0.y = acc[mi][ni][1] + 0.1f * noise_s[(b + 1) * 132 + hl];
            *(float2*)(g_xwn + (size_t)t * BH + (size_t)(h0 + hl) * 64 + b) = v0;
            float2 v1;
            v1.x = acc[mi][ni][2] + 0.1f * noise_s[(b + 0) * 132 + hl + 8];
            v1.y = acc[mi][ni][3] + 0.1f * noise_s[(b + 1) * 132 + hl + 8];
            *(float2*)(g_xwn + (size_t)t * BH + (size_t)(h0 + hl + 8) * 64 + b) = v1;
        }
    }
}

// ---------------- k_out (HMMA): out = sigmoid(hidden) @ W_ho^T + b_ho ----------------
__global__ void __launch_bounds__(256)
k_out(const float* __restrict__ hidden, const float* __restrict__ bho,
      float* __restrict__ outp) {
    extern __shared__ __align__(1024) char sm[];
    const uint32_t smb = smem_u32(sm);
    const int tid = threadIdx.x;
    const int wid = tid >> 5;
    const int lane = tid & 31;
    const int o0 = blockIdx.x * 128;
    const int m0 = blockIdx.y * 64;

    const int warp_m0 = (wid >> 1) * 32;
    const int warp_n0 = (wid & 1) * 32;
    const uint32_t aA = smb + O_W +
        (uint32_t)((warp_m0 + (lane & 15)) * PITCH + ((lane >> 4) << 4));
    const uint32_t bA = smb + O_B +
        (uint32_t)((warp_n0 + (lane & 7) + ((lane >> 4) << 3)) * PITCH +
                   (((lane >> 3) & 1) << 4));

    float acc[2][4][4];
#pragma unroll
    for (int mi = 0; mi < 2; mi++)
#pragma unroll
        for (int ni = 0; ni < 4; ni++)
#pragma unroll
            for (int j = 0; j < 4; j++) acc[mi][ni][j] = 0.0f;

    for (int c = 0; c < 8; c++) {
        for (int it = 0; it < 16; it++) {
            const int r = it * 8 + wid;
            uint4 hv = *(const uint4*)(g_who + (size_t)(o0 + r) * NH + c * 256 + lane * 8);
            *(uint4*)(sm + O_W + r * PITCH + lane * 16) = hv;
        }
#pragma unroll
        for (int it = 0; it < 8; it++) {
            const int m = it * 8 + wid;
            const float* hr = hidden + (size_t)(m0 + m) * NH + c * 256 + lane * 8;
            float4 v0 = *(const float4*)(hr);
            float4 v1 = *(const float4*)(hr + 4);
            uint4 hv = make_uint4(
                h2pack(sigmoidf_(v0.x), sigmoidf_(v0.y)),
                h2pack(sigmoidf_(v0.z), sigmoidf_(v0.w)),
                h2pack(sigmoidf_(v1.x), sigmoidf_(v1.y)),
                h2pack(sigmoidf_(v1.z), sigmoidf_(v1.w)));
            *(uint4*)(sm + O_B + m * PITCH + lane * 16) = hv;
        }
        __syncthreads();
#pragma unroll 4
        for (int ks = 0; ks < 16; ks++) {
            const uint32_t ko = ks * 32;
            unsigned am[2][4], bm[4][2];
            ldsm4(am[0], aA + ko);
            ldsm4(am[1], aA + ko + 16 * PITCH);
            ldsm4(&bm[0][0], bA + ko);
            ldsm4(&bm[2][0], bA + ko + 16 * PITCH);
#pragma unroll
            for (int mi = 0; mi < 2; mi++)
#pragma unroll
                for (int ni = 0; ni < 4; ni++)
                    mma_f16(acc[mi][ni], am[mi], bm[ni]);
        }
        __syncthreads();
    }

    const int rq = lane >> 2;
    const int cq = (lane & 3) * 2;
#pragma unroll
    for (int mi = 0; mi < 2; mi++) {
        const int o = o0 + warp_m0 + mi * 16 + rq;
        const float bv0 = bho[o];
        const float bv8 = bho[o + 8];
#pragma unroll
        for (int ni = 0; ni < 4; ni++) {
            const int m = m0 + warp_n0 + ni * 8 + cq;
            outp[(size_t)(m + 0) * NO + o] = acc[mi][ni][0] + bv0;
            outp[(size_t)(m + 1) * NO + o] = acc[mi][ni][1] + bv0;
            outp[(size_t)(m + 0) * NO + o + 8] = acc[mi][ni][2] + bv8;
            outp[(size_t)(m + 1) * NO + o + 8] = acc[mi][ni][3] + bv8;
        }
    }
}

extern "C" void kernel_launch(void* const* d_in, const int* in_sizes, int n_in,
                              void* d_out, int out_size) {
    const float* x     = (const float*)d_in[0];   // [B,S,I]
    const float* h0    = (const float*)d_in[1];   // [B,1,H]
    const float* Wih   = (const float*)d_in[2];   // [H,I]
    const float* Whh   = (const float*)d_in[3];   // [H,H]
    const float* Who   = (const float*)d_in[4];   // [O,H]
    const float* bho   = (const float*)d_in[5];   // [O]
    const float* noise = (const float*)d_in[6];   // [S,B,1,H]
    float* outp = (float*)d_out;

    const size_t OUTE = (size_t)NB * NS * NO;
    const size_t HIDE = (size_t)NB * NS * NH;

    float* hidden;
    if ((size_t)out_size >= OUTE + HIDE) {
        hidden = outp + OUTE;   // harness output = concat(out, hidden)
    } else {
        void* p = nullptr;
        cudaGetSymbolAddress(&p, g_hid_fb);
        hidden = (float*)p;
    }

    cudaFuncSetAttribute(k_recur, cudaFuncAttributeMaxDynamicSharedMemorySize, R_TOTAL);
    cudaFuncSetAttribute(k_xw, cudaFuncAttributeMaxDynamicSharedMemorySize, X_TOTAL);
    cudaFuncSetAttribute(k_out, cudaFuncAttributeMaxDynamicSharedMemorySize, O_TOTAL);

    // 0. one-time weight conversion (fp32 -> fp16)
    k_convW<<<(NH * NI + NO * NH) / 256, 256>>>(Wih, Who);

    // 1. input projection (HMMA) + noise fold, layout [t][h][b]
    k_xw<<<dim3(NH / 128, NS), 256, X_TOTAL>>>(x, noise);

    // 2. full recurrence: persistent HMMA kernel, 4-CTA band clusters,
    //    DSMEM partial exchange + transposed sigh (coalesced publish)
    k_recur<<<GB, 256, R_TOTAL>>>(h0, Whh, hidden);

    // 3. output projection (HMMA)
    k_out<<<dim3(NO / 128, (NB * NS) / 64), 256, O_TOTAL>>>(hidden, bho, outp);
}